// round 14
// baseline (speedup 1.0000x reference)
#include <cuda_runtime.h>
#include <cstdint>

// ---------------- problem constants ----------------
#define B_    16
#define N_    4096
#define CIN_  64
#define COUT_ 128
#define K_    16
#define M_    1024
#define EPS_  1e-5f

typedef unsigned long long ull;

// ---------------- static device scratch ----------------
__device__ int      g_fps[B_ * M_];
__device__ float    g_h[(size_t)B_ * N_ * COUT_];       // 32 MB
__device__ float    g_ps[1024 * COUT_];
__device__ float    g_ps2[1024 * COUT_];
__device__ float    g_scale[COUT_];
__device__ float    g_shift[COUT_];
__device__ float    g_d2[(size_t)B_ * M_ * N_];         // 256 MB
__device__ unsigned g_prog[B_];                          // fps progress per batch
__device__ unsigned g_lin_done;                          // linear chunk count (512)
__device__ unsigned g_stats_done;                        // stats channels done (128)
__device__ unsigned g_gemm_done[B_ * 8];                 // per (b,mt) gemm nt-count (32)
__device__ unsigned g_fps_smid[B_];                      // physical SM of each fps block
__device__ unsigned g_smid_valid[B_];                    // smid published flag
__device__ unsigned g_topk_done;                         // finished topk blocks

// ---------------- acquire/release helpers ----------------
__device__ __forceinline__ unsigned ld_acq(const unsigned* p) {
    unsigned v;
    asm volatile("ld.acquire.gpu.u32 %0, [%1];" : "=r"(v) : "l"(p) : "memory");
    return v;
}
__device__ __forceinline__ void st_rel(unsigned* p, unsigned v) {
    asm volatile("st.release.gpu.u32 [%0], %1;" :: "l"(p), "r"(v) : "memory");
}

// ---------------- packed f32x2 helpers (per-lane .rn == scalar rounding) ----
__device__ __forceinline__ ull pk2(float lo, float hi) {
    ull r; asm("mov.b64 %0, {%1, %2};" : "=l"(r) : "f"(lo), "f"(hi)); return r;
}
__device__ __forceinline__ void upk2(ull v, float& lo, float& hi) {
    asm("mov.b64 {%0, %1}, %2;" : "=f"(lo), "=f"(hi) : "l"(v));
}
__device__ __forceinline__ ull add2(ull a, ull b) {
    ull r; asm("add.rn.f32x2 %0, %1, %2;" : "=l"(r) : "l"(a), "l"(b)); return r;
}
__device__ __forceinline__ ull mul2(ull a, ull b) {
    ull r; asm("mul.rn.f32x2 %0, %1, %2;" : "=l"(r) : "l"(a), "l"(b)); return r;
}
__device__ __forceinline__ ull fma2(ull a, ull b, ull c) {
    ull r; asm("fma.rn.f32x2 %0, %1, %2, %3;" : "=l"(r) : "l"(a), "l"(b), "l"(c)); return r;
}

// ---------------- layout: wave-1-resident mega ----------------
#define WORKERS    396                            // 132 SMs x 3 slots
#define MEGA_BLKS  444                            // 148 x 3, all wave-1
#define LIN_CHUNKS 512
#define GEMM_TILES (B_ * 8 * 32)                  // 4096

// =====================================================================
// FPS body: packed f32x2 distances (.rn, exact), umin/umax selection.
// Publishes its physical SM id so overlapped topk blocks can avoid it.
// =====================================================================
__device__ __forceinline__ void fps_body(const float* __restrict__ pos,
                                         float* sp, int b, int t)
{
    __shared__ ull sred[2][8];

    const int lane = t & 31;
    const int w    = t >> 5;
    const float* pb = pos + (size_t)b * N_ * 3;

    if (t == 0) {
        unsigned smid; asm volatile("mov.u32 %0, %%smid;" : "=r"(smid));
        g_fps_smid[b] = smid;
        __threadfence();
        st_rel(&g_smid_valid[b], 1u);
    }

    for (int i = t; i < (3 * N_) / 4; i += 256)
        ((float4*)sp)[i] = ((const float4*)pb)[i];
    __syncthreads();

    const int base = t * 16;
    ull px2[8], py2[8], pz2[8];
    unsigned mind_u[16];                       // bit patterns of non-neg floats
    const unsigned INIT_U = __float_as_uint(1e10f);
#pragma unroll
    for (int j = 0; j < 8; j++) {
        int a = base + 2 * j;
        px2[j] = pk2(sp[a * 3 + 0], sp[a * 3 + 3]);
        py2[j] = pk2(sp[a * 3 + 1], sp[a * 3 + 4]);
        pz2[j] = pk2(sp[a * 3 + 2], sp[a * 3 + 5]);
        mind_u[2 * j] = INIT_U; mind_u[2 * j + 1] = INIT_U;
    }

    int widx = 0;
    if (t == 0) g_fps[b * M_] = 0;

    for (int m = 1; m < M_; m++) {
        const int p = m & 1;
        const float qx = sp[widx * 3 + 0];
        const float qy = sp[widx * 3 + 1];
        const float qz = sp[widx * 3 + 2];
        const ull nqx = pk2(-qx, -qx);
        const ull nqy = pk2(-qy, -qy);
        const ull nqz = pk2(-qz, -qz);

        // exact: dx = p + (-q); s = (dx*dx + dy*dy) + dz*dz  (all .rn, no FMA)
#pragma unroll
        for (int j = 0; j < 8; j++) {
            ull dx = add2(px2[j], nqx);
            ull dy = add2(py2[j], nqy);
            ull dz = add2(pz2[j], nqz);
            ull s  = add2(add2(mul2(dx, dx), mul2(dy, dy)), mul2(dz, dz));
            float s0, s1; upk2(s, s0, s1);
            mind_u[2 * j]     = min(mind_u[2 * j],     __float_as_uint(s0));
            mind_u[2 * j + 1] = min(mind_u[2 * j + 1], __float_as_uint(s1));
        }

        // max tree (umax level 1 on alu, fmax levels 2-4 on fma)
        unsigned u0 = max(mind_u[0],  mind_u[1]);
        unsigned u1 = max(mind_u[2],  mind_u[3]);
        unsigned u2 = max(mind_u[4],  mind_u[5]);
        unsigned u3 = max(mind_u[6],  mind_u[7]);
        unsigned u4 = max(mind_u[8],  mind_u[9]);
        unsigned u5 = max(mind_u[10], mind_u[11]);
        unsigned u6 = max(mind_u[12], mind_u[13]);
        unsigned u7 = max(mind_u[14], mind_u[15]);
        float f0 = fmaxf(__uint_as_float(u0), __uint_as_float(u1));
        float f1 = fmaxf(__uint_as_float(u2), __uint_as_float(u3));
        float f2 = fmaxf(__uint_as_float(u4), __uint_as_float(u5));
        float f3 = fmaxf(__uint_as_float(u6), __uint_as_float(u7));
        f0 = fmaxf(f0, f1); f2 = fmaxf(f2, f3);
        const unsigned vb = __float_as_uint(fmaxf(f0, f2));

        // parallel integer equality mask -> lowest matching index
        unsigned mk = 0;
#pragma unroll
        for (int j = 0; j < 16; j++)
            if (mind_u[j] == vb) mk |= 1u << j;
        const int bi = base + (__ffs(mk) - 1);

        // warp argmax (REDUX; lowest matching lane owns -> lowest index)
        unsigned vm  = __reduce_max_sync(0xffffffffu, vb);
        unsigned msk = __ballot_sync(0xffffffffu, vb == vm);
        if (lane == __ffs(msk) - 1)
            sred[p][w] = ((ull)vm << 32) | (unsigned)(N_ - 1 - bi);
        __syncthreads();

        ull r = sred[p][0];
#pragma unroll
        for (int j = 1; j < 8; j++) { ull x = sred[p][j]; r = (x > r) ? x : r; }
        widx = N_ - 1 - (int)(unsigned)(r & 0xffffffffu);

        if (t == 0) {
            g_fps[b * M_ + m] = widx;
            if ((m & 127) == 127) {
                __threadfence();
                st_rel(&g_prog[b], (unsigned)(m + 1));
            }
        }
    }
}

// =====================================================================
// Parasite: pins a slot on an FPS SM until that batch's FPS is done.
// =====================================================================
__device__ __forceinline__ void parasite_body(int b, int t)
{
    if (t == 0)
        while (ld_acq(&g_prog[b]) < (unsigned)M_) __nanosleep(1024);
    __syncthreads();
}

// =====================================================================
// Linear chunk: 128 points, 256 threads (o = channel, g = point-half).
// =====================================================================
__device__ __forceinline__ void linear_body(const float* __restrict__ feat,
                                            const float* __restrict__ W,
                                            const float* __restrict__ bias,
                                            float4* fs, int blk, int t)
{
    const int o = t & 127;
    const int g = t >> 7;
    const size_t p0 = (size_t)blk * 128;

    float w[64];
#pragma unroll
    for (int c = 0; c < 64; c++) w[c] = W[c * COUT_ + o];
    const float bo = bias[o];

    const float4* fg = (const float4*)(feat + p0 * CIN_);
#pragma unroll
    for (int i = 0; i < 8; i++) fs[t + i * 256] = fg[t + i * 256];
    __syncthreads();

    float s1 = 0.f, s2 = 0.f;
    const int pbeg = g * 64;
    for (int p = pbeg; p < pbeg + 64; p++) {
        float acc = bo;
#pragma unroll
        for (int cq = 0; cq < 16; cq++) {
            float4 v = fs[p * 16 + cq];
            acc = fmaf(v.x, w[cq * 4 + 0], acc);
            acc = fmaf(v.y, w[cq * 4 + 1], acc);
            acc = fmaf(v.z, w[cq * 4 + 2], acc);
            acc = fmaf(v.w, w[cq * 4 + 3], acc);
        }
        g_h[(p0 + p) * COUT_ + o] = acc;
        s1 += acc;
        s2 = fmaf(acc, acc, s2);
    }
    g_ps [(blk * 2 + g) * COUT_ + o] = s1;
    g_ps2[(blk * 2 + g) * COUT_ + o] = s2;

    __threadfence();
    __syncthreads();
    if (t == 0) atomicAdd(&g_lin_done, 1u);
    __syncthreads();                       // fs reuse safety for next chunk
}

// =====================================================================
// Stats: one channel; polls all linear chunks done.
// =====================================================================
__device__ __forceinline__ void stats_body(const float* __restrict__ gamma,
                                           const float* __restrict__ beta,
                                           int c, int t)
{
    __shared__ float r1[256], r2[256];

    if (t == 0) while (ld_acq(&g_lin_done) < (unsigned)LIN_CHUNKS) __nanosleep(256);
    __syncthreads();

    float s1 = 0.f, s2 = 0.f;
    for (int i = t; i < 1024; i += 256) {
        s1 += g_ps [i * COUT_ + c];
        s2 += g_ps2[i * COUT_ + c];
    }
    r1[t] = s1; r2[t] = s2;
    __syncthreads();
    for (int o = 128; o > 0; o >>= 1) {
        if (t < o) { r1[t] += r1[t + o]; r2[t] += r2[t + o]; }
        __syncthreads();
    }
    if (t == 0) {
        const float inv = 1.0f / (float)(B_ * N_);
        float mean = r1[0] * inv;
        float var  = r2[0] * inv - mean * mean;
        float sc   = gamma[c] * rsqrtf(var + EPS_);
        g_scale[c] = sc;
        g_shift[c] = beta[c] - mean * sc;
        __threadfence();
        atomicAdd(&g_stats_done, 1u);
    }
    __syncthreads();
}

// =====================================================================
// GEMM tile: polls fps progress, stages, computes kk (bit-identical
// fmaf order), packed-FMA GEMM, signals per-(b,mt) completion.
// =====================================================================
__device__ __forceinline__ void gemm_body(const float* __restrict__ feat,
                                          float* smg, int gidx, int t)
{
    __shared__ int   qrow[128];
    __shared__ float skk[128];

    const int mt = gidx >> 9;                 // / (B_*32)
    const int b  = (gidx >> 5) & 15;
    const int nt = gidx & 31;

    float* Qs = smg;                          // [64][128] d-major
    float* Fs = smg + 64 * 128;               // [64][128] d-major
    const float* fb = feat + (size_t)b * N_ * CIN_;

    if (t == 0)
        while (ld_acq(&g_prog[b]) < (unsigned)((mt + 1) * 128)) __nanosleep(128);
    __syncthreads();

    if (t < 128) qrow[t] = g_fps[b * M_ + mt * 128 + t];
    __syncthreads();

    {   // staging: 2 threads per row, 8 float4 each, transposed write
        const int row  = t >> 1;
        const int half = (t & 1) * 8;
        const float4* srcQ = (const float4*)(fb + (size_t)qrow[row] * CIN_);
        const float4* srcF = (const float4*)(fb + (size_t)(nt * 128 + row) * CIN_);
#pragma unroll
        for (int i = 0; i < 8; i++) {
            float4 v = srcQ[half + i];
            int d = (half + i) * 4;
            Qs[(d + 0) * 128 + row] = v.x;
            Qs[(d + 1) * 128 + row] = v.y;
            Qs[(d + 2) * 128 + row] = v.z;
            Qs[(d + 3) * 128 + row] = v.w;
        }
#pragma unroll
        for (int i = 0; i < 8; i++) {
            float4 v = srcF[half + i];
            int d = (half + i) * 4;
            Fs[(d + 0) * 128 + row] = v.x;
            Fs[(d + 1) * 128 + row] = v.y;
            Fs[(d + 2) * 128 + row] = v.z;
            Fs[(d + 3) * 128 + row] = v.w;
        }
    }
    __syncthreads();

    if (t < 128) {                             // per-column |f|^2
        float s = 0.f;
#pragma unroll 8
        for (int d = 0; d < 64; d++) {
            float v = Fs[d * 128 + t];
            s = fmaf(v, v, s);
        }
        skk[t] = s;
    }
    __syncthreads();

    const int tx = t & 15, ty = t >> 4;
    const int n0 = tx * 8, m0 = ty * 8;

    ull acc[8][4];
#pragma unroll
    for (int i = 0; i < 8; i++)
#pragma unroll
        for (int j = 0; j < 4; j++) acc[i][j] = 0ull;

#pragma unroll 4
    for (int d = 0; d < 64; d++) {
        ulonglong2 fA = *(const ulonglong2*)&Fs[d * 128 + n0];
        ulonglong2 fB = *(const ulonglong2*)&Fs[d * 128 + n0 + 4];
        float4 qa = *(const float4*)&Qs[d * 128 + m0];
        float4 qb = *(const float4*)&Qs[d * 128 + m0 + 4];
        float qv[8] = {qa.x, qa.y, qa.z, qa.w, qb.x, qb.y, qb.z, qb.w};
#pragma unroll
        for (int i = 0; i < 8; i++) {
            ull qq = pk2(qv[i], qv[i]);
            acc[i][0] = fma2(qq, fA.x, acc[i][0]);
            acc[i][1] = fma2(qq, fA.y, acc[i][1]);
            acc[i][2] = fma2(qq, fB.x, acc[i][2]);
            acc[i][3] = fma2(qq, fB.y, acc[i][3]);
        }
    }

    ull kk01 = pk2(skk[n0 + 0], skk[n0 + 1]);
    ull kk23 = pk2(skk[n0 + 2], skk[n0 + 3]);
    ull kk45 = pk2(skk[n0 + 4], skk[n0 + 5]);
    ull kk67 = pk2(skk[n0 + 6], skk[n0 + 7]);
    const ull m2 = pk2(-2.0f, -2.0f);

    float* out = g_d2 + ((size_t)(b * M_ + mt * 128 + m0)) * N_ + nt * 128 + n0;
#pragma unroll
    for (int i = 0; i < 8; i++) {
        ulonglong2 o1, o2;
        o1.x = fma2(acc[i][0], m2, kk01);
        o1.y = fma2(acc[i][1], m2, kk23);
        o2.x = fma2(acc[i][2], m2, kk45);
        o2.y = fma2(acc[i][3], m2, kk67);
        *(ulonglong2*)(out + (size_t)i * N_)     = o1;
        *(ulonglong2*)(out + (size_t)i * N_ + 4) = o2;
    }

    __threadfence();
    __syncthreads();
    if (t == 0) atomicAdd(&g_gemm_done[(b << 3) + mt], 1u);
    __syncthreads();                       // smem reuse safety for next tile
}

// =====================================================================
// Mega: 444 blocks, ALL wave-1 resident. Every block triggers PDL at
// entry so the topk kernel can dispatch into spare thread slots.
//   bid%148<16: round0 fps, rounds1-2 parasites (pin FPS SMs)
//   else: persistent worker: lin chunks -> stats(ch) -> gemm tiles.
// =====================================================================
__global__ void __launch_bounds__(256) mega_kernel(const float* __restrict__ pos,
                                                   const float* __restrict__ feat,
                                                   const float* __restrict__ W,
                                                   const float* __restrict__ bias,
                                                   const float* __restrict__ gamma,
                                                   const float* __restrict__ beta)
{
    extern __shared__ float smem[];
    cudaTriggerProgrammaticLaunchCompletion();

    const int bid   = blockIdx.x;
    const int t     = threadIdx.x;
    const int r     = bid % 148;
    const int round = bid / 148;

    if (r < 16) {
        if (round == 0) fps_body(pos, smem, r, t);
        else            parasite_body(r, t);
        return;
    }

    const int w = round * 132 + (r - 16);          // worker id 0..395

    for (int blk = w; blk < LIN_CHUNKS; blk += WORKERS)
        linear_body(feat, W, bias, (float4*)smem, blk, t);

    if (w < COUT_)
        stats_body(gamma, beta, w, t);

    for (int g = w; g < GEMM_TILES; g += WORKERS)   // mt ascends with g
        gemm_body(feat, smem, g, t);
}

// =====================================================================
// Topk (PDL secondary): mt-major block order, self-gated on flags.
// Blocks on an active FPS SM spin until that FPS finishes (no issue
// contention). Last finishing block resets all flags for replay.
// =====================================================================
#define CAND_CAP 1024

__global__ void __launch_bounds__(256) topk_gather_kernel(const float* __restrict__ pos,
                                                          float* __restrict__ out)
{
    __shared__ float sT[8];
    __shared__ int   scnt;
    __shared__ ull   scand[CAND_CAP];
    __shared__ int   snbr[K_];

    const int bid = blockIdx.x;
    const int mt  = bid >> 11;                   // mt-major dispatch order
    const int b   = (bid >> 7) & 15;
    const int ml  = bid & 127;
    const int q   = b * M_ + mt * 128 + ml;

    const int t    = threadIdx.x;
    const int lane = t & 31;
    const int wrp  = t >> 5;

    if (t == 0) {
        // avoid contending with a live FPS block on this SM
        unsigned my; asm volatile("mov.u32 %0, %%smid;" : "=r"(my));
        for (int i = 0; i < B_; i++) {
            while (ld_acq(&g_smid_valid[i]) == 0u) __nanosleep(128);
            if (g_fps_smid[i] == my)
                while (ld_acq(&g_prog[i]) < (unsigned)M_) __nanosleep(2048);
        }
        while (ld_acq(&g_stats_done) < (unsigned)COUT_)   __nanosleep(256);
        while (ld_acq(&g_gemm_done[(b << 3) + mt]) < 32u) __nanosleep(256);
    }
    __syncthreads();

    // ---- load 16 contiguous row values (streaming) ----
    float v[16];
    {
        const float4* src = (const float4*)(g_d2 + (size_t)q * N_) + t * 4;
        float4 a  = __ldcs(src + 0);
        float4 b4 = __ldcs(src + 1);
        float4 c4 = __ldcs(src + 2);
        float4 d4 = __ldcs(src + 3);
        v[0]=a.x;  v[1]=a.y;  v[2]=a.z;  v[3]=a.w;
        v[4]=b4.x; v[5]=b4.y; v[6]=b4.z; v[7]=b4.w;
        v[8]=c4.x; v[9]=c4.y; v[10]=c4.z; v[11]=c4.w;
        v[12]=d4.x; v[13]=d4.y; v[14]=d4.z; v[15]=d4.w;
    }

    // ---- local min ----
    float lm = v[0];
#pragma unroll
    for (int j = 1; j < 16; j++) lm = fminf(lm, v[j]);

    // ---- warp bitonic sort (ascending) of the 32 local minima ----
    float s = lm;
#pragma unroll
    for (int k = 2; k <= 32; k <<= 1) {
#pragma unroll
        for (int j = k >> 1; j > 0; j >>= 1) {
            float o = __shfl_xor_sync(0xffffffffu, s, j);
            bool lower = (lane & j) == 0;
            bool asc   = (lane & k) == 0;
            s = (asc == lower) ? fminf(s, o) : fmaxf(s, o);
        }
    }
    if (lane == 15) sT[wrp] = s;   // warp's 16th smallest local-min (upper bound)
    if (t == 0) scnt = 0;
    __syncthreads();

    float T = sT[0];
#pragma unroll
    for (int j = 1; j < 8; j++) T = fminf(T, sT[j]);

    // ---- scan-based compaction of candidates (val <= T) ----
    int c = 0;
#pragma unroll
    for (int j = 0; j < 16; j++) c += (v[j] <= T) ? 1 : 0;

    int sc = c;
#pragma unroll
    for (int o = 1; o < 32; o <<= 1) {
        int x = __shfl_up_sync(0xffffffffu, sc, o);
        if (lane >= o) sc += x;
    }
    const int wtot = __shfl_sync(0xffffffffu, sc, 31);
    int basew = 0;
    if (lane == 31) basew = atomicAdd(&scnt, wtot);
    basew = __shfl_sync(0xffffffffu, basew, 31);

    int posn = basew + (sc - c);
#pragma unroll
    for (int j = 0; j < 16; j++) {
        if (v[j] <= T) {
            unsigned sv = __float_as_uint(v[j]);
            sv ^= (unsigned)((int)sv >> 31) | 0x80000000u;     // sortable
            if (posn < CAND_CAP)
                scand[posn] = ((ull)sv << 12) | (unsigned)(t * 16 + j);
            posn++;
        }
    }
    __syncthreads();

    // ---- warp 0: exact sorted extraction of 16 smallest keys ----
    if (wrp == 0) {
        int cnt = scnt; if (cnt > CAND_CAP) cnt = CAND_CAP;
        const int nslots = (cnt + 31) >> 5;

        ull best = ~0ull; int bslot = -1;
        for (int i = 0; i < nslots; i++) {
            int sl = lane + i * 32;
            if (sl < cnt) { ull kk = scand[sl]; if (kk < best) { best = kk; bslot = sl; } }
        }
        for (int k = 0; k < K_; k++) {
            ull r2 = best;
#pragma unroll
            for (int o = 16; o > 0; o >>= 1) {
                ull x = __shfl_xor_sync(0xffffffffu, r2, o);
                r2 = (x < r2) ? x : r2;
            }
            if (lane == 0) snbr[k] = (int)(r2 & 0xfffu);
            if (best == r2) {                       // unique owner rescans
                scand[bslot] = ~0ull;
                best = ~0ull; bslot = -1;
                for (int i = 0; i < nslots; i++) {
                    int sl = lane + i * 32;
                    if (sl < cnt) { ull kk = scand[sl]; if (kk < best) { best = kk; bslot = sl; } }
                }
            }
        }
    }
    __syncthreads();

    // ---- fused gather + BN-folded max-pool + positions/batch ----
    const size_t OFF_POS   = (size_t)B_ * M_ * COUT_;
    const size_t OFF_BATCH = OFF_POS + (size_t)B_ * M_ * 3;

    if (t < COUT_) {
        const float* hb = g_h + (size_t)b * N_ * COUT_;
        float mx = -__int_as_float(0x7f800000);
        float mn =  __int_as_float(0x7f800000);
#pragma unroll
        for (int k = 0; k < K_; k++) {
            float val = hb[(size_t)snbr[k] * COUT_ + t];
            mx = fmaxf(mx, val);
            mn = fminf(mn, val);
        }
        const float sc2 = g_scale[t];
        out[(size_t)q * COUT_ + t] = fmaf(sc2, (sc2 >= 0.f) ? mx : mn, g_shift[t]);
    } else {
        int r2 = t - COUT_;
        if (r2 < 3) {
            int fi = g_fps[q];
            out[OFF_POS + (size_t)q * 3 + r2] = pos[((size_t)b * N_ + fi) * 3 + r2];
        }
        if (r2 == 3) out[OFF_BATCH + q] = (float)b;
    }

    // ---- last-block flag reset (replay-safe, race-free) ----
    __syncthreads();
    if (t == 0) {
        __threadfence();
        if (atomicAdd(&g_topk_done, 1u) == (unsigned)(B_ * M_ - 1)) {
            for (int i = 0; i < B_; i++) {
                g_prog[i] = 0u; g_smid_valid[i] = 0u; g_fps_smid[i] = 0xffffffffu;
            }
            for (int i = 0; i < B_ * 8; i++) g_gemm_done[i] = 0u;
            g_lin_done   = 0u;
            g_stats_done = 0u;
            g_topk_done  = 0u;
        }
    }
}

// =====================================================================
// launch: mega, then topk with Programmatic Stream Serialization (PDL)
// so topk blocks dispatch into spare slots while mega still runs.
// =====================================================================
extern "C" void kernel_launch(void* const* d_in, const int* in_sizes, int n_in,
                              void* d_out, int out_size)
{
    const float* features  = (const float*)d_in[0];
    const float* positions = (const float*)d_in[1];
    // d_in[2] = batch (int64): values deterministic (b), unused
    const float* W     = (const float*)d_in[3];
    const float* bias  = (const float*)d_in[4];
    const float* gamma = (const float*)d_in[5];
    const float* beta  = (const float*)d_in[6];
    float* out = (float*)d_out;

    const int mega_smem = 2 * 64 * 128 * 4;          // 64 KB (3 blocks/SM)
    cudaFuncSetAttribute(mega_kernel, cudaFuncAttributeMaxDynamicSharedMemorySize, mega_smem);

    mega_kernel<<<MEGA_BLKS, 256, mega_smem>>>(positions, features, W, bias,
                                               gamma, beta);

    cudaLaunchConfig_t cfg = {};
    cfg.gridDim  = dim3(B_ * M_);
    cfg.blockDim = dim3(256);
    cfg.dynamicSmemBytes = 0;
    cfg.stream = 0;
    cudaLaunchAttribute attrs[1];
    attrs[0].id = cudaLaunchAttributeProgrammaticStreamSerialization;
    attrs[0].val.programmaticStreamSerializationAllowed = 1;
    cfg.attrs = attrs;
    cfg.numAttrs = 1;
    cudaLaunchKernelEx(&cfg, topk_gather_kernel, positions, out);
}

// round 15
// speedup vs baseline: 1.3512x; 1.3512x over previous
#include <cuda_runtime.h>
#include <cstdint>

// ---------------- problem constants ----------------
#define B_    16
#define N_    4096
#define CIN_  64
#define COUT_ 128
#define K_    16
#define M_    1024
#define EPS_  1e-5f

typedef unsigned long long ull;

// ---------------- static device scratch ----------------
__device__ int      g_fps[B_ * M_];
__device__ float    g_h[(size_t)B_ * N_ * COUT_];       // 32 MB
__device__ float    g_ps[1024 * COUT_];
__device__ float    g_ps2[1024 * COUT_];
__device__ float    g_scale[COUT_];
__device__ float    g_shift[COUT_];
__device__ float    g_d2[(size_t)B_ * M_ * N_];         // 256 MB
__device__ float    g_tmin[(size_t)B_ * M_ * 32];       // per-row per-tile min (2 MB)
__device__ unsigned g_prog[B_];                          // fps progress per batch
__device__ unsigned g_lin_done;                          // linear completion count

// ---------------- acquire/release helpers ----------------
__device__ __forceinline__ unsigned ld_acq(const unsigned* p) {
    unsigned v;
    asm volatile("ld.acquire.gpu.u32 %0, [%1];" : "=r"(v) : "l"(p) : "memory");
    return v;
}
__device__ __forceinline__ void st_rel(unsigned* p, unsigned v) {
    asm volatile("st.release.gpu.u32 [%0], %1;" :: "l"(p), "r"(v) : "memory");
}

// ---------------- packed f32x2 helpers (per-lane .rn == scalar rounding) ----
__device__ __forceinline__ ull pk2(float lo, float hi) {
    ull r; asm("mov.b64 %0, {%1, %2};" : "=l"(r) : "f"(lo), "f"(hi)); return r;
}
__device__ __forceinline__ void upk2(ull v, float& lo, float& hi) {
    asm("mov.b64 {%0, %1}, %2;" : "=f"(lo), "=f"(hi) : "l"(v));
}
__device__ __forceinline__ ull add2(ull a, ull b) {
    ull r; asm("add.rn.f32x2 %0, %1, %2;" : "=l"(r) : "l"(a), "l"(b)); return r;
}
__device__ __forceinline__ ull mul2(ull a, ull b) {
    ull r; asm("mul.rn.f32x2 %0, %1, %2;" : "=l"(r) : "l"(a), "l"(b)); return r;
}
__device__ __forceinline__ ull fma2(ull a, ull b, ull c) {
    ull r; asm("fma.rn.f32x2 %0, %1, %2, %3;" : "=l"(r) : "l"(a), "l"(b), "l"(c)); return r;
}

// ---------------- work layout (after removing special bids) ----------------
#define LIN_BLKS   512
#define STAT_BLKS  128
#define GEMM_BLKS  (B_ * 8 * 32)                  // 4096
#define WORK_BLKS  (LIN_BLKS + STAT_BLKS + GEMM_BLKS)   // 4736
#define SPECIALS   48                              // 16 fps + 32 parasites
#define MEGA_BLKS  (WORK_BLKS + SPECIALS)          // 4784

// =====================================================================
// FPS body: 256 threads, 16 pts/thread, packed f32x2 distances (.rn,
// exact). Issue-floor-bound on the mandatory packed ops; selection on
// alu pipe (bit-exact for non-negative floats).
// =====================================================================
__device__ __forceinline__ void fps_body(const float* __restrict__ pos,
                                         float* sp, int b, int t)
{
    __shared__ ull sred[2][8];

    const int lane = t & 31;
    const int w    = t >> 5;
    const float* pb = pos + (size_t)b * N_ * 3;

    for (int i = t; i < (3 * N_) / 4; i += 256)
        ((float4*)sp)[i] = ((const float4*)pb)[i];
    __syncthreads();

    const int base = t * 16;
    ull px2[8], py2[8], pz2[8];
    unsigned mind_u[16];                       // bit patterns of non-neg floats
    const unsigned INIT_U = __float_as_uint(1e10f);
#pragma unroll
    for (int j = 0; j < 8; j++) {
        int a = base + 2 * j;
        px2[j] = pk2(sp[a * 3 + 0], sp[a * 3 + 3]);
        py2[j] = pk2(sp[a * 3 + 1], sp[a * 3 + 4]);
        pz2[j] = pk2(sp[a * 3 + 2], sp[a * 3 + 5]);
        mind_u[2 * j] = INIT_U; mind_u[2 * j + 1] = INIT_U;
    }

    int widx = 0;
    if (t == 0) g_fps[b * M_] = 0;

    for (int m = 1; m < M_; m++) {
        const int p = m & 1;
        const float qx = sp[widx * 3 + 0];
        const float qy = sp[widx * 3 + 1];
        const float qz = sp[widx * 3 + 2];
        const ull nqx = pk2(-qx, -qx);
        const ull nqy = pk2(-qy, -qy);
        const ull nqz = pk2(-qz, -qz);

        // exact: dx = p + (-q); s = (dx*dx + dy*dy) + dz*dz  (all .rn, no FMA)
#pragma unroll
        for (int j = 0; j < 8; j++) {
            ull dx = add2(px2[j], nqx);
            ull dy = add2(py2[j], nqy);
            ull dz = add2(pz2[j], nqz);
            ull s  = add2(add2(mul2(dx, dx), mul2(dy, dy)), mul2(dz, dz));
            float s0, s1; upk2(s, s0, s1);
            mind_u[2 * j]     = min(mind_u[2 * j],     __float_as_uint(s0));
            mind_u[2 * j + 1] = min(mind_u[2 * j + 1], __float_as_uint(s1));
        }

        // max tree: level 1 on alu (umax), levels 2-4 on fma (fmaxf)
        unsigned u0 = max(mind_u[0],  mind_u[1]);
        unsigned u1 = max(mind_u[2],  mind_u[3]);
        unsigned u2 = max(mind_u[4],  mind_u[5]);
        unsigned u3 = max(mind_u[6],  mind_u[7]);
        unsigned u4 = max(mind_u[8],  mind_u[9]);
        unsigned u5 = max(mind_u[10], mind_u[11]);
        unsigned u6 = max(mind_u[12], mind_u[13]);
        unsigned u7 = max(mind_u[14], mind_u[15]);
        float f0 = fmaxf(__uint_as_float(u0), __uint_as_float(u1));
        float f1 = fmaxf(__uint_as_float(u2), __uint_as_float(u3));
        float f2 = fmaxf(__uint_as_float(u4), __uint_as_float(u5));
        float f3 = fmaxf(__uint_as_float(u6), __uint_as_float(u7));
        f0 = fmaxf(f0, f1); f2 = fmaxf(f2, f3);
        const unsigned vb = __float_as_uint(fmaxf(f0, f2));

        // parallel integer equality mask -> lowest matching index
        unsigned mk = 0;
#pragma unroll
        for (int j = 0; j < 16; j++)
            if (mind_u[j] == vb) mk |= 1u << j;
        const int bi = base + (__ffs(mk) - 1);

        // warp argmax: REDUX on value bits (d>=0 -> monotone); lowest lane
        // holding vmax writes its own candidate (lowest lane = lowest indices)
        unsigned vm  = __reduce_max_sync(0xffffffffu, vb);
        unsigned msk = __ballot_sync(0xffffffffu, vb == vm);
        if (lane == __ffs(msk) - 1)
            sred[p][w] = ((ull)vm << 32) | (unsigned)(N_ - 1 - bi);
        __syncthreads();

        // all threads redundantly scan 8 entries (ping-pong protects vs next iter)
        ull r = sred[p][0];
#pragma unroll
        for (int j = 1; j < 8; j++) { ull x = sred[p][j]; r = (x > r) ? x : r; }
        widx = N_ - 1 - (int)(unsigned)(r & 0xffffffffu);

        if (t == 0) {
            g_fps[b * M_ + m] = widx;
            if ((m & 127) == 127) {
                __threadfence();
                st_rel(&g_prog[b], (unsigned)(m + 1));
            }
        }
    }
}

// =====================================================================
// Parasite: pins a slot on an FPS SM until that batch's FPS is done.
// =====================================================================
__device__ __forceinline__ void parasite_body(int b, int t)
{
    if (t == 0)
        while (ld_acq(&g_prog[b]) < (unsigned)M_) __nanosleep(1024);
    __syncthreads();
}

// =====================================================================
// Linear body: 128 points per block, 256 threads (o = channel, g = half).
// =====================================================================
__device__ __forceinline__ void linear_body(const float* __restrict__ feat,
                                            const float* __restrict__ W,
                                            const float* __restrict__ bias,
                                            float4* fs, int blk, int t)
{
    const int o = t & 127;
    const int g = t >> 7;
    const size_t p0 = (size_t)blk * 128;

    float w[64];
#pragma unroll
    for (int c = 0; c < 64; c++) w[c] = W[c * COUT_ + o];
    const float bo = bias[o];

    const float4* fg = (const float4*)(feat + p0 * CIN_);
#pragma unroll
    for (int i = 0; i < 8; i++) fs[t + i * 256] = fg[t + i * 256];
    __syncthreads();

    float s1 = 0.f, s2 = 0.f;
    const int pbeg = g * 64;
    for (int p = pbeg; p < pbeg + 64; p++) {
        float acc = bo;
#pragma unroll
        for (int cq = 0; cq < 16; cq++) {
            float4 v = fs[p * 16 + cq];
            acc = fmaf(v.x, w[cq * 4 + 0], acc);
            acc = fmaf(v.y, w[cq * 4 + 1], acc);
            acc = fmaf(v.z, w[cq * 4 + 2], acc);
            acc = fmaf(v.w, w[cq * 4 + 3], acc);
        }
        g_h[(p0 + p) * COUT_ + o] = acc;
        s1 += acc;
        s2 = fmaf(acc, acc, s2);
    }
    g_ps [(blk * 2 + g) * COUT_ + o] = s1;
    g_ps2[(blk * 2 + g) * COUT_ + o] = s2;

    __threadfence();
    __syncthreads();
    if (t == 0) atomicAdd(&g_lin_done, 1u);
}

// =====================================================================
// Stats body: one channel per block; polls linear completion.
// =====================================================================
__device__ __forceinline__ void stats_body(const float* __restrict__ gamma,
                                           const float* __restrict__ beta,
                                           int c, int t)
{
    __shared__ float r1[256], r2[256];

    if (t == 0) while (ld_acq(&g_lin_done) < (unsigned)LIN_BLKS) __nanosleep(256);
    __syncthreads();

    float s1 = 0.f, s2 = 0.f;
    for (int i = t; i < 1024; i += 256) {
        s1 += g_ps [i * COUT_ + c];
        s2 += g_ps2[i * COUT_ + c];
    }
    r1[t] = s1; r2[t] = s2;
    __syncthreads();
    for (int o = 128; o > 0; o >>= 1) {
        if (t < o) { r1[t] += r1[t + o]; r2[t] += r2[t + o]; }
        __syncthreads();
    }
    if (t == 0) {
        const float inv = 1.0f / (float)(B_ * N_);
        float mean = r1[0] * inv;
        float var  = r2[0] * inv - mean * mean;
        float sc   = gamma[c] * rsqrtf(var + EPS_);
        g_scale[c] = sc;
        g_shift[c] = beta[c] - mean * sc;
    }
}

// =====================================================================
// GEMM body: polls fps progress, stages, computes kk (bit-identical
// fmaf order), packed-FMA GEMM. NEW: also emits per-row tile-min
// (g_tmin[q][nt]) for topk pruning -- free under the FPS shadow.
// =====================================================================
__device__ __forceinline__ void gemm_body(const float* __restrict__ feat,
                                          float* smg, int gidx, int t)
{
    __shared__ int   qrow[128];
    __shared__ float skk[128];

    const int mt = gidx >> 9;                 // / (B_*32)
    const int b  = (gidx >> 5) & 15;
    const int nt = gidx & 31;

    float* Qs = smg;                          // [64][128] d-major
    float* Fs = smg + 64 * 128;               // [64][128] d-major
    const float* fb = feat + (size_t)b * N_ * CIN_;

    if (t == 0)
        while (ld_acq(&g_prog[b]) < (unsigned)((mt + 1) * 128)) __nanosleep(128);
    __syncthreads();

    if (t < 128) qrow[t] = g_fps[b * M_ + mt * 128 + t];
    __syncthreads();

    {   // staging: 2 threads per row, 8 float4 each, transposed write
        const int row  = t >> 1;
        const int half = (t & 1) * 8;
        const float4* srcQ = (const float4*)(fb + (size_t)qrow[row] * CIN_);
        const float4* srcF = (const float4*)(fb + (size_t)(nt * 128 + row) * CIN_);
#pragma unroll
        for (int i = 0; i < 8; i++) {
            float4 v = srcQ[half + i];
            int d = (half + i) * 4;
            Qs[(d + 0) * 128 + row] = v.x;
            Qs[(d + 1) * 128 + row] = v.y;
            Qs[(d + 2) * 128 + row] = v.z;
            Qs[(d + 3) * 128 + row] = v.w;
        }
#pragma unroll
        for (int i = 0; i < 8; i++) {
            float4 v = srcF[half + i];
            int d = (half + i) * 4;
            Fs[(d + 0) * 128 + row] = v.x;
            Fs[(d + 1) * 128 + row] = v.y;
            Fs[(d + 2) * 128 + row] = v.z;
            Fs[(d + 3) * 128 + row] = v.w;
        }
    }
    __syncthreads();

    // per-column |f|^2, same sequential fmaf order over d
    if (t < 128) {
        float s = 0.f;
#pragma unroll 8
        for (int d = 0; d < 64; d++) {
            float v = Fs[d * 128 + t];
            s = fmaf(v, v, s);
        }
        skk[t] = s;
    }
    __syncthreads();

    const int tx = t & 15, ty = t >> 4;
    const int n0 = tx * 8, m0 = ty * 8;

    ull acc[8][4];
#pragma unroll
    for (int i = 0; i < 8; i++)
#pragma unroll
        for (int j = 0; j < 4; j++) acc[i][j] = 0ull;

#pragma unroll 4
    for (int d = 0; d < 64; d++) {
        ulonglong2 fA = *(const ulonglong2*)&Fs[d * 128 + n0];
        ulonglong2 fB = *(const ulonglong2*)&Fs[d * 128 + n0 + 4];
        float4 qa = *(const float4*)&Qs[d * 128 + m0];
        float4 qb = *(const float4*)&Qs[d * 128 + m0 + 4];
        float qv[8] = {qa.x, qa.y, qa.z, qa.w, qb.x, qb.y, qb.z, qb.w};
#pragma unroll
        for (int i = 0; i < 8; i++) {
            ull qq = pk2(qv[i], qv[i]);
            acc[i][0] = fma2(qq, fA.x, acc[i][0]);
            acc[i][1] = fma2(qq, fA.y, acc[i][1]);
            acc[i][2] = fma2(qq, fB.x, acc[i][2]);
            acc[i][3] = fma2(qq, fB.y, acc[i][3]);
        }
    }

    ull kk01 = pk2(skk[n0 + 0], skk[n0 + 1]);
    ull kk23 = pk2(skk[n0 + 2], skk[n0 + 3]);
    ull kk45 = pk2(skk[n0 + 4], skk[n0 + 5]);
    ull kk67 = pk2(skk[n0 + 6], skk[n0 + 7]);
    const ull m2 = pk2(-2.0f, -2.0f);

    float* out = g_d2 + ((size_t)(b * M_ + mt * 128 + m0)) * N_ + nt * 128 + n0;
#pragma unroll
    for (int i = 0; i < 8; i++) {
        ulonglong2 o1, o2;
        o1.x = fma2(acc[i][0], m2, kk01);
        o1.y = fma2(acc[i][1], m2, kk23);
        o2.x = fma2(acc[i][2], m2, kk45);
        o2.y = fma2(acc[i][3], m2, kk67);
        *(ulonglong2*)(out + (size_t)i * N_)     = o1;
        *(ulonglong2*)(out + (size_t)i * N_ + 4) = o2;

        // per-row tile min: 8 local values, then half-warp (16 tx lanes) min
        float a0, a1, a2, a3, a4, a5, a6, a7;
        upk2(o1.x, a0, a1); upk2(o1.y, a2, a3);
        upk2(o2.x, a4, a5); upk2(o2.y, a6, a7);
        float rm = fminf(fminf(fminf(a0, a1), fminf(a2, a3)),
                         fminf(fminf(a4, a5), fminf(a6, a7)));
#pragma unroll
        for (int o = 1; o <= 8; o <<= 1)
            rm = fminf(rm, __shfl_xor_sync(0xffffffffu, rm, o));
        if (tx == 0)
            g_tmin[(size_t)(b * M_ + mt * 128 + m0 + i) * 32 + nt] = rm;
    }
}

// =====================================================================
// Mega kernel with SM isolation (identical structure to R13/best).
// =====================================================================
__global__ void __launch_bounds__(256) mega_kernel(const float* __restrict__ pos,
                                                   const float* __restrict__ feat,
                                                   const float* __restrict__ W,
                                                   const float* __restrict__ bias,
                                                   const float* __restrict__ gamma,
                                                   const float* __restrict__ beta)
{
    extern __shared__ float smem[];
    const int bid   = blockIdx.x;
    const int t     = threadIdx.x;
    const int r     = bid % 148;
    const int round = bid / 148;

    if (r < 16 && round <= 2) {
        if (round == 0) fps_body(pos, smem, r, t);
        else            parasite_body(r, t);
        return;
    }

    int w;
    if      (bid < 148)      w = bid - 16;
    else if (bid < 296)      w = bid - 32;
    else                     w = bid - 48;

    if (w < LIN_BLKS)
        linear_body(feat, W, bias, (float4*)smem, w, t);
    else if (w < LIN_BLKS + STAT_BLKS)
        stats_body(gamma, beta, w - LIN_BLKS, t);
    else
        gemm_body(feat, smem, w - LIN_BLKS - STAT_BLKS, t);
}

// =====================================================================
// Tile-min-pruned exact top-K=16 + fused gather/maxpool/epilogue.
// T16 = 16th smallest of the 32 tile minima (provable upper bound on
// the true 16th-smallest). Only tiles with tmin <= T16 are read;
// candidates = values <= T16 (provable superset of the top-16).
// =====================================================================
#define CAND_CAP 1024

__global__ void __launch_bounds__(256) topk_gather_kernel(const float* __restrict__ pos,
                                                          float* __restrict__ out)
{
    __shared__ int   stile[32];
    __shared__ int   sS;
    __shared__ float sTv;
    __shared__ int   scnt;
    __shared__ ull   scand[CAND_CAP];
    __shared__ int   snbr[K_];

    const int q    = blockIdx.x;                 // b*M + m
    const int t    = threadIdx.x;
    const int lane = t & 31;
    const int wrp  = t >> 5;

    if (q == 0) {                                // flag reset for next replay
        if (t < B_)   g_prog[t] = 0u;
        if (t == 200) g_lin_done = 0u;
    }

    if (t == 0) scnt = 0;

    // ---- warp 0: threshold + tile selection from the 32 tile minima ----
    if (wrp == 0) {
        const float v0 = g_tmin[(size_t)q * 32 + lane];
        float s = v0;
#pragma unroll
        for (int k = 2; k <= 32; k <<= 1) {
#pragma unroll
            for (int j = k >> 1; j > 0; j >>= 1) {
                float o = __shfl_xor_sync(0xffffffffu, s, j);
                bool lower = (lane & j) == 0;
                bool asc   = (lane & k) == 0;
                s = (asc == lower) ? fminf(s, o) : fmaxf(s, o);
            }
        }
        const float T = __shfl_sync(0xffffffffu, s, 15);   // 16th smallest
        unsigned m = __ballot_sync(0xffffffffu, v0 <= T);
        if (v0 <= T)
            stile[__popc(m & ((1u << lane) - 1u))] = lane;  // compacted tile ids
        if (lane == 0) { sS = __popc(m); sTv = T; }
    }
    __syncthreads();

    const int   S = sS;
    const float T = sTv;

    // ---- filter selected tiles; scan-compact candidates (val <= T) ----
    const float4* row4 = (const float4*)(g_d2 + (size_t)q * N_);
    for (int c = t; c < S * 32; c += 256) {       // S*32 multiple of 32: warp-uniform
        const int nt = stile[c >> 5];
        const int of = c & 31;
        float4 val = __ldcs(row4 + nt * 32 + of);
        float vv[4] = {val.x, val.y, val.z, val.w};

        int cc = 0;
#pragma unroll
        for (int j = 0; j < 4; j++) cc += (vv[j] <= T) ? 1 : 0;

        int sc = cc;                               // warp inclusive scan
#pragma unroll
        for (int o = 1; o < 32; o <<= 1) {
            int x = __shfl_up_sync(0xffffffffu, sc, o);
            if (lane >= o) sc += x;
        }
        const int wtot = __shfl_sync(0xffffffffu, sc, 31);
        int basew = 0;
        if (lane == 31) basew = atomicAdd(&scnt, wtot);
        basew = __shfl_sync(0xffffffffu, basew, 31);

        int posn = basew + (sc - cc);
#pragma unroll
        for (int j = 0; j < 4; j++) {
            if (vv[j] <= T) {
                unsigned sv = __float_as_uint(vv[j]);
                sv ^= (unsigned)((int)sv >> 31) | 0x80000000u;     // sortable
                if (posn < CAND_CAP)
                    scand[posn] = ((ull)sv << 12) | (unsigned)(nt * 128 + of * 4 + j);
                posn++;
            }
        }
    }
    __syncthreads();

    // ---- warp 0: exact sorted extraction of 16 smallest keys ----
    if (wrp == 0) {
        int cnt = scnt; if (cnt > CAND_CAP) cnt = CAND_CAP;
        const int nslots = (cnt + 31) >> 5;

        ull best = ~0ull; int bslot = -1;
        for (int i = 0; i < nslots; i++) {
            int sl = lane + i * 32;
            if (sl < cnt) { ull kk = scand[sl]; if (kk < best) { best = kk; bslot = sl; } }
        }
        for (int k = 0; k < K_; k++) {
            ull r2 = best;
#pragma unroll
            for (int o = 16; o > 0; o >>= 1) {
                ull x = __shfl_xor_sync(0xffffffffu, r2, o);
                r2 = (x < r2) ? x : r2;
            }
            if (lane == 0) snbr[k] = (int)(r2 & 0xfffu);
            if (best == r2) {                       // unique owner rescans
                scand[bslot] = ~0ull;
                best = ~0ull; bslot = -1;
                for (int i = 0; i < nslots; i++) {
                    int sl = lane + i * 32;
                    if (sl < cnt) { ull kk = scand[sl]; if (kk < best) { best = kk; bslot = sl; } }
                }
            }
        }
    }
    __syncthreads();

    // ---- fused gather + BN-folded max-pool + positions/batch ----
    const size_t OFF_POS   = (size_t)B_ * M_ * COUT_;
    const size_t OFF_BATCH = OFF_POS + (size_t)B_ * M_ * 3;
    const int b = q >> 10;

    if (t < COUT_) {
        const float* hb = g_h + (size_t)b * N_ * COUT_;
        float mx = -__int_as_float(0x7f800000);
        float mn =  __int_as_float(0x7f800000);
#pragma unroll
        for (int k = 0; k < K_; k++) {
            float val = hb[(size_t)snbr[k] * COUT_ + t];
            mx = fmaxf(mx, val);
            mn = fminf(mn, val);
        }
        const float sc2 = g_scale[t];
        out[(size_t)q * COUT_ + t] = fmaf(sc2, (sc2 >= 0.f) ? mx : mn, g_shift[t]);
    } else {
        int r2 = t - COUT_;
        if (r2 < 3) {
            int fi = g_fps[q];
            out[OFF_POS + (size_t)q * 3 + r2] = pos[((size_t)b * N_ + fi) * 3 + r2];
        }
        if (r2 == 3) out[OFF_BATCH + q] = (float)b;
    }
}

// =====================================================================
// launch
// =====================================================================
extern "C" void kernel_launch(void* const* d_in, const int* in_sizes, int n_in,
                              void* d_out, int out_size)
{
    const float* features  = (const float*)d_in[0];
    const float* positions = (const float*)d_in[1];
    // d_in[2] = batch (int64): values deterministic (b), unused
    const float* W     = (const float*)d_in[3];
    const float* bias  = (const float*)d_in[4];
    const float* gamma = (const float*)d_in[5];
    const float* beta  = (const float*)d_in[6];
    float* out = (float*)d_out;

    const int mega_smem = 2 * 64 * 128 * 4;          // 64 KB (3 blocks/SM)
    cudaFuncSetAttribute(mega_kernel, cudaFuncAttributeMaxDynamicSharedMemorySize, mega_smem);

    mega_kernel<<<MEGA_BLKS, 256, mega_smem>>>(positions, features, W, bias,
                                               gamma, beta);
    topk_gather_kernel<<<B_ * M_, 256>>>(positions, out);
}

// round 16
// speedup vs baseline: 1.4871x; 1.1006x over previous
#include <cuda_runtime.h>
#include <cstdint>

// ---------------- problem constants ----------------
#define B_    16
#define N_    4096
#define CIN_  64
#define COUT_ 128
#define K_    16
#define M_    1024
#define EPS_  1e-5f

typedef unsigned long long ull;

// ---------------- static device scratch ----------------
__device__ int      g_fps[B_ * M_];
__device__ float    g_h[(size_t)B_ * N_ * COUT_];       // 32 MB
__device__ float    g_ps[1024 * COUT_];
__device__ float    g_ps2[1024 * COUT_];
__device__ float    g_scale[COUT_];
__device__ float    g_shift[COUT_];
__device__ float    g_d2[(size_t)B_ * M_ * N_];         // 256 MB
__device__ float    g_tmin16[(size_t)B_ * M_ * 32 * 16]; // per-row/tile/tx partial min (32 MB)
__device__ unsigned g_prog[B_];                          // fps progress per batch
__device__ unsigned g_lin_done;                          // linear completion count

// ---------------- acquire/release helpers ----------------
__device__ __forceinline__ unsigned ld_acq(const unsigned* p) {
    unsigned v;
    asm volatile("ld.acquire.gpu.u32 %0, [%1];" : "=r"(v) : "l"(p) : "memory");
    return v;
}
__device__ __forceinline__ void st_rel(unsigned* p, unsigned v) {
    asm volatile("st.release.gpu.u32 [%0], %1;" :: "l"(p), "r"(v) : "memory");
}

// ---------------- packed f32x2 helpers (per-lane .rn == scalar rounding) ----
__device__ __forceinline__ ull pk2(float lo, float hi) {
    ull r; asm("mov.b64 %0, {%1, %2};" : "=l"(r) : "f"(lo), "f"(hi)); return r;
}
__device__ __forceinline__ void upk2(ull v, float& lo, float& hi) {
    asm("mov.b64 {%0, %1}, %2;" : "=f"(lo), "=f"(hi) : "l"(v));
}
__device__ __forceinline__ ull add2(ull a, ull b) {
    ull r; asm("add.rn.f32x2 %0, %1, %2;" : "=l"(r) : "l"(a), "l"(b)); return r;
}
__device__ __forceinline__ ull mul2(ull a, ull b) {
    ull r; asm("mul.rn.f32x2 %0, %1, %2;" : "=l"(r) : "l"(a), "l"(b)); return r;
}
__device__ __forceinline__ ull fma2(ull a, ull b, ull c) {
    ull r; asm("fma.rn.f32x2 %0, %1, %2, %3;" : "=l"(r) : "l"(a), "l"(b), "l"(c)); return r;
}

// ---------------- work layout (after removing special bids) ----------------
#define LIN_BLKS   512
#define STAT_BLKS  128
#define GEMM_BLKS  (B_ * 8 * 32)                  // 4096
#define WORK_BLKS  (LIN_BLKS + STAT_BLKS + GEMM_BLKS)   // 4736
#define SPECIALS   48                              // 16 fps + 32 parasites
#define MEGA_BLKS  (WORK_BLKS + SPECIALS)          // 4784

// =====================================================================
// FPS body: 256 threads, 16 pts/thread, packed f32x2 distances (.rn,
// exact). Selection on alu pipe (bit-exact for non-negative floats).
// =====================================================================
__device__ __forceinline__ void fps_body(const float* __restrict__ pos,
                                         float* sp, int b, int t)
{
    __shared__ ull sred[2][8];

    const int lane = t & 31;
    const int w    = t >> 5;
    const float* pb = pos + (size_t)b * N_ * 3;

    for (int i = t; i < (3 * N_) / 4; i += 256)
        ((float4*)sp)[i] = ((const float4*)pb)[i];
    __syncthreads();

    const int base = t * 16;
    ull px2[8], py2[8], pz2[8];
    unsigned mind_u[16];                       // bit patterns of non-neg floats
    const unsigned INIT_U = __float_as_uint(1e10f);
#pragma unroll
    for (int j = 0; j < 8; j++) {
        int a = base + 2 * j;
        px2[j] = pk2(sp[a * 3 + 0], sp[a * 3 + 3]);
        py2[j] = pk2(sp[a * 3 + 1], sp[a * 3 + 4]);
        pz2[j] = pk2(sp[a * 3 + 2], sp[a * 3 + 5]);
        mind_u[2 * j] = INIT_U; mind_u[2 * j + 1] = INIT_U;
    }

    int widx = 0;
    if (t == 0) g_fps[b * M_] = 0;

    for (int m = 1; m < M_; m++) {
        const int p = m & 1;
        const float qx = sp[widx * 3 + 0];
        const float qy = sp[widx * 3 + 1];
        const float qz = sp[widx * 3 + 2];
        const ull nqx = pk2(-qx, -qx);
        const ull nqy = pk2(-qy, -qy);
        const ull nqz = pk2(-qz, -qz);

        // exact: dx = p + (-q); s = (dx*dx + dy*dy) + dz*dz  (all .rn, no FMA)
#pragma unroll
        for (int j = 0; j < 8; j++) {
            ull dx = add2(px2[j], nqx);
            ull dy = add2(py2[j], nqy);
            ull dz = add2(pz2[j], nqz);
            ull s  = add2(add2(mul2(dx, dx), mul2(dy, dy)), mul2(dz, dz));
            float s0, s1; upk2(s, s0, s1);
            mind_u[2 * j]     = min(mind_u[2 * j],     __float_as_uint(s0));
            mind_u[2 * j + 1] = min(mind_u[2 * j + 1], __float_as_uint(s1));
        }

        // max tree: level 1 on alu (umax), levels 2-4 on fma (fmaxf)
        unsigned u0 = max(mind_u[0],  mind_u[1]);
        unsigned u1 = max(mind_u[2],  mind_u[3]);
        unsigned u2 = max(mind_u[4],  mind_u[5]);
        unsigned u3 = max(mind_u[6],  mind_u[7]);
        unsigned u4 = max(mind_u[8],  mind_u[9]);
        unsigned u5 = max(mind_u[10], mind_u[11]);
        unsigned u6 = max(mind_u[12], mind_u[13]);
        unsigned u7 = max(mind_u[14], mind_u[15]);
        float f0 = fmaxf(__uint_as_float(u0), __uint_as_float(u1));
        float f1 = fmaxf(__uint_as_float(u2), __uint_as_float(u3));
        float f2 = fmaxf(__uint_as_float(u4), __uint_as_float(u5));
        float f3 = fmaxf(__uint_as_float(u6), __uint_as_float(u7));
        f0 = fmaxf(f0, f1); f2 = fmaxf(f2, f3);
        const unsigned vb = __float_as_uint(fmaxf(f0, f2));

        // parallel integer equality mask -> lowest matching index
        unsigned mk = 0;
#pragma unroll
        for (int j = 0; j < 16; j++)
            if (mind_u[j] == vb) mk |= 1u << j;
        const int bi = base + (__ffs(mk) - 1);

        // warp argmax: REDUX on value bits (d>=0 -> monotone); lowest lane
        // holding vmax writes its own candidate (lowest lane = lowest indices)
        unsigned vm  = __reduce_max_sync(0xffffffffu, vb);
        unsigned msk = __ballot_sync(0xffffffffu, vb == vm);
        if (lane == __ffs(msk) - 1)
            sred[p][w] = ((ull)vm << 32) | (unsigned)(N_ - 1 - bi);
        __syncthreads();

        // all threads redundantly scan 8 entries (ping-pong protects vs next iter)
        ull r = sred[p][0];
#pragma unroll
        for (int j = 1; j < 8; j++) { ull x = sred[p][j]; r = (x > r) ? x : r; }
        widx = N_ - 1 - (int)(unsigned)(r & 0xffffffffu);

        if (t == 0) {
            g_fps[b * M_ + m] = widx;
            if ((m & 127) == 127) {
                __threadfence();
                st_rel(&g_prog[b], (unsigned)(m + 1));
            }
        }
    }
}

// =====================================================================
// Parasite: pins a slot on an FPS SM until that batch's FPS is done.
// =====================================================================
__device__ __forceinline__ void parasite_body(int b, int t)
{
    if (t == 0)
        while (ld_acq(&g_prog[b]) < (unsigned)M_) __nanosleep(1024);
    __syncthreads();
}

// =====================================================================
// Linear body: 128 points per block, 256 threads (o = channel, g = half).
// =====================================================================
__device__ __forceinline__ void linear_body(const float* __restrict__ feat,
                                            const float* __restrict__ W,
                                            const float* __restrict__ bias,
                                            float4* fs, int blk, int t)
{
    const int o = t & 127;
    const int g = t >> 7;
    const size_t p0 = (size_t)blk * 128;

    float w[64];
#pragma unroll
    for (int c = 0; c < 64; c++) w[c] = W[c * COUT_ + o];
    const float bo = bias[o];

    const float4* fg = (const float4*)(feat + p0 * CIN_);
#pragma unroll
    for (int i = 0; i < 8; i++) fs[t + i * 256] = fg[t + i * 256];
    __syncthreads();

    float s1 = 0.f, s2 = 0.f;
    const int pbeg = g * 64;
    for (int p = pbeg; p < pbeg + 64; p++) {
        float acc = bo;
#pragma unroll
        for (int cq = 0; cq < 16; cq++) {
            float4 v = fs[p * 16 + cq];
            acc = fmaf(v.x, w[cq * 4 + 0], acc);
            acc = fmaf(v.y, w[cq * 4 + 1], acc);
            acc = fmaf(v.z, w[cq * 4 + 2], acc);
            acc = fmaf(v.w, w[cq * 4 + 3], acc);
        }
        g_h[(p0 + p) * COUT_ + o] = acc;
        s1 += acc;
        s2 = fmaf(acc, acc, s2);
    }
    g_ps [(blk * 2 + g) * COUT_ + o] = s1;
    g_ps2[(blk * 2 + g) * COUT_ + o] = s2;

    __threadfence();
    __syncthreads();
    if (t == 0) atomicAdd(&g_lin_done, 1u);
}

// =====================================================================
// Stats body: one channel per block; polls linear completion.
// =====================================================================
__device__ __forceinline__ void stats_body(const float* __restrict__ gamma,
                                           const float* __restrict__ beta,
                                           int c, int t)
{
    __shared__ float r1[256], r2[256];

    if (t == 0) while (ld_acq(&g_lin_done) < (unsigned)LIN_BLKS) __nanosleep(256);
    __syncthreads();

    float s1 = 0.f, s2 = 0.f;
    for (int i = t; i < 1024; i += 256) {
        s1 += g_ps [i * COUT_ + c];
        s2 += g_ps2[i * COUT_ + c];
    }
    r1[t] = s1; r2[t] = s2;
    __syncthreads();
    for (int o = 128; o > 0; o >>= 1) {
        if (t < o) { r1[t] += r1[t + o]; r2[t] += r2[t + o]; }
        __syncthreads();
    }
    if (t == 0) {
        const float inv = 1.0f / (float)(B_ * N_);
        float mean = r1[0] * inv;
        float var  = r2[0] * inv - mean * mean;
        float sc   = gamma[c] * rsqrtf(var + EPS_);
        g_scale[c] = sc;
        g_shift[c] = beta[c] - mean * sc;
    }
}

// =====================================================================
// GEMM body: polls fps progress, stages, computes kk (bit-identical
// fmaf order), packed-FMA GEMM. Emits PER-THREAD partial row minima
// (7 FMNMX + 1 STG per row; no shuffles, no barriers) for topk pruning.
// =====================================================================
__device__ __forceinline__ void gemm_body(const float* __restrict__ feat,
                                          float* smg, int gidx, int t)
{
    __shared__ int   qrow[128];
    __shared__ float skk[128];

    const int mt = gidx >> 9;                 // / (B_*32)
    const int b  = (gidx >> 5) & 15;
    const int nt = gidx & 31;

    float* Qs = smg;                          // [64][128] d-major
    float* Fs = smg + 64 * 128;               // [64][128] d-major
    const float* fb = feat + (size_t)b * N_ * CIN_;

    if (t == 0)
        while (ld_acq(&g_prog[b]) < (unsigned)((mt + 1) * 128)) __nanosleep(128);
    __syncthreads();

    if (t < 128) qrow[t] = g_fps[b * M_ + mt * 128 + t];
    __syncthreads();

    {   // staging: 2 threads per row, 8 float4 each, transposed write
        const int row  = t >> 1;
        const int half = (t & 1) * 8;
        const float4* srcQ = (const float4*)(fb + (size_t)qrow[row] * CIN_);
        const float4* srcF = (const float4*)(fb + (size_t)(nt * 128 + row) * CIN_);
#pragma unroll
        for (int i = 0; i < 8; i++) {
            float4 v = srcQ[half + i];
            int d = (half + i) * 4;
            Qs[(d + 0) * 128 + row] = v.x;
            Qs[(d + 1) * 128 + row] = v.y;
            Qs[(d + 2) * 128 + row] = v.z;
            Qs[(d + 3) * 128 + row] = v.w;
        }
#pragma unroll
        for (int i = 0; i < 8; i++) {
            float4 v = srcF[half + i];
            int d = (half + i) * 4;
            Fs[(d + 0) * 128 + row] = v.x;
            Fs[(d + 1) * 128 + row] = v.y;
            Fs[(d + 2) * 128 + row] = v.z;
            Fs[(d + 3) * 128 + row] = v.w;
        }
    }
    __syncthreads();

    // per-column |f|^2, same sequential fmaf order over d
    if (t < 128) {
        float s = 0.f;
#pragma unroll 8
        for (int d = 0; d < 64; d++) {
            float v = Fs[d * 128 + t];
            s = fmaf(v, v, s);
        }
        skk[t] = s;
    }
    __syncthreads();

    const int tx = t & 15, ty = t >> 4;
    const int n0 = tx * 8, m0 = ty * 8;

    ull acc[8][4];
#pragma unroll
    for (int i = 0; i < 8; i++)
#pragma unroll
        for (int j = 0; j < 4; j++) acc[i][j] = 0ull;

#pragma unroll 4
    for (int d = 0; d < 64; d++) {
        ulonglong2 fA = *(const ulonglong2*)&Fs[d * 128 + n0];
        ulonglong2 fB = *(const ulonglong2*)&Fs[d * 128 + n0 + 4];
        float4 qa = *(const float4*)&Qs[d * 128 + m0];
        float4 qb = *(const float4*)&Qs[d * 128 + m0 + 4];
        float qv[8] = {qa.x, qa.y, qa.z, qa.w, qb.x, qb.y, qb.z, qb.w};
#pragma unroll
        for (int i = 0; i < 8; i++) {
            ull qq = pk2(qv[i], qv[i]);
            acc[i][0] = fma2(qq, fA.x, acc[i][0]);
            acc[i][1] = fma2(qq, fA.y, acc[i][1]);
            acc[i][2] = fma2(qq, fB.x, acc[i][2]);
            acc[i][3] = fma2(qq, fB.y, acc[i][3]);
        }
    }

    ull kk01 = pk2(skk[n0 + 0], skk[n0 + 1]);
    ull kk23 = pk2(skk[n0 + 2], skk[n0 + 3]);
    ull kk45 = pk2(skk[n0 + 4], skk[n0 + 5]);
    ull kk67 = pk2(skk[n0 + 6], skk[n0 + 7]);
    const ull m2 = pk2(-2.0f, -2.0f);

    float* out = g_d2 + ((size_t)(b * M_ + mt * 128 + m0)) * N_ + nt * 128 + n0;
    float* tm  = g_tmin16 + ((size_t)(b * M_ + mt * 128 + m0)) * 512 + nt * 16 + tx;
#pragma unroll
    for (int i = 0; i < 8; i++) {
        ulonglong2 o1, o2;
        o1.x = fma2(acc[i][0], m2, kk01);
        o1.y = fma2(acc[i][1], m2, kk23);
        o2.x = fma2(acc[i][2], m2, kk45);
        o2.y = fma2(acc[i][3], m2, kk67);
        *(ulonglong2*)(out + (size_t)i * N_)     = o1;
        *(ulonglong2*)(out + (size_t)i * N_ + 4) = o2;

        // per-thread partial min of this row's 8 values (no shfl, no barrier)
        float a0, a1, a2, a3, a4, a5, a6, a7;
        upk2(o1.x, a0, a1); upk2(o1.y, a2, a3);
        upk2(o2.x, a4, a5); upk2(o2.y, a6, a7);
        tm[(size_t)i * 512] =
            fminf(fminf(fminf(a0, a1), fminf(a2, a3)),
                  fminf(fminf(a4, a5), fminf(a6, a7)));
    }
}

// =====================================================================
// Mega kernel with SM isolation (identical structure to R13/best).
// =====================================================================
__global__ void __launch_bounds__(256) mega_kernel(const float* __restrict__ pos,
                                                   const float* __restrict__ feat,
                                                   const float* __restrict__ W,
                                                   const float* __restrict__ bias,
                                                   const float* __restrict__ gamma,
                                                   const float* __restrict__ beta)
{
    extern __shared__ float smem[];
    const int bid   = blockIdx.x;
    const int t     = threadIdx.x;
    const int r     = bid % 148;
    const int round = bid / 148;

    if (r < 16 && round <= 2) {
        if (round == 0) fps_body(pos, smem, r, t);
        else            parasite_body(r, t);
        return;
    }

    int w;
    if      (bid < 148)      w = bid - 16;
    else if (bid < 296)      w = bid - 32;
    else                     w = bid - 48;

    if (w < LIN_BLKS)
        linear_body(feat, W, bias, (float4*)smem, w, t);
    else if (w < LIN_BLKS + STAT_BLKS)
        stats_body(gamma, beta, w - LIN_BLKS, t);
    else
        gemm_body(feat, smem, w - LIN_BLKS - STAT_BLKS, t);
}

// =====================================================================
// Tile-min-pruned exact top-K=16 + fused gather/maxpool/epilogue.
// Folds 512 per-thread partials -> 32 tile minima; T16 = 16th smallest
// tile-min (provable upper bound on the true 16th-smallest). Only
// tiles with tmin <= T16 are read; candidates = values <= T16.
// =====================================================================
#define CAND_CAP 1024

__global__ void __launch_bounds__(256) topk_gather_kernel(const float* __restrict__ pos,
                                                          float* __restrict__ out)
{
    __shared__ float stmin[32];
    __shared__ int   stile[32];
    __shared__ int   sS;
    __shared__ float sTv;
    __shared__ int   scnt;
    __shared__ ull   scand[CAND_CAP];
    __shared__ int   snbr[K_];

    const int q    = blockIdx.x;                 // b*M + m
    const int t    = threadIdx.x;
    const int lane = t & 31;
    const int wrp  = t >> 5;

    if (q == 0) {                                // flag reset for next replay
        if (t < B_)   g_prog[t] = 0u;
        if (t == 200) g_lin_done = 0u;
    }
    if (t == 0) scnt = 0;

    // ---- fold 512 partials -> 32 tile minima (8 lanes per tile) ----
    {
        const int nt = t >> 3;                    // tile 0..31
        const int e  = t & 7;
        const float* pm = g_tmin16 + (size_t)q * 512 + nt * 16 + e;
        float mn = fminf(pm[0], pm[8]);
        mn = fminf(mn, __shfl_xor_sync(0xffffffffu, mn, 1));
        mn = fminf(mn, __shfl_xor_sync(0xffffffffu, mn, 2));
        mn = fminf(mn, __shfl_xor_sync(0xffffffffu, mn, 4));
        if (e == 0) stmin[nt] = mn;
    }
    __syncthreads();

    // ---- warp 0: threshold + tile selection from the 32 tile minima ----
    if (wrp == 0) {
        const float v0 = stmin[lane];
        float s = v0;
#pragma unroll
        for (int k = 2; k <= 32; k <<= 1) {
#pragma unroll
            for (int j = k >> 1; j > 0; j >>= 1) {
                float o = __shfl_xor_sync(0xffffffffu, s, j);
                bool lower = (lane & j) == 0;
                bool asc   = (lane & k) == 0;
                s = (asc == lower) ? fminf(s, o) : fmaxf(s, o);
            }
        }
        const float T = __shfl_sync(0xffffffffu, s, 15);   // 16th smallest
        unsigned m = __ballot_sync(0xffffffffu, v0 <= T);
        if (v0 <= T)
            stile[__popc(m & ((1u << lane) - 1u))] = lane;  // compacted tile ids
        if (lane == 0) { sS = __popc(m); sTv = T; }
    }
    __syncthreads();

    const int   S = sS;
    const float T = sTv;

    // ---- filter selected tiles; scan-compact candidates (val <= T) ----
    const float4* row4 = (const float4*)(g_d2 + (size_t)q * N_);
    for (int c = t; c < S * 32; c += 256) {       // S*32 multiple of 32: warp-uniform
        const int nt = stile[c >> 5];
        const int of = c & 31;
        float4 val = __ldcs(row4 + nt * 32 + of);
        float vv[4] = {val.x, val.y, val.z, val.w};

        int cc = 0;
#pragma unroll
        for (int j = 0; j < 4; j++) cc += (vv[j] <= T) ? 1 : 0;

        int sc = cc;                               // warp inclusive scan
#pragma unroll
        for (int o = 1; o < 32; o <<= 1) {
            int x = __shfl_up_sync(0xffffffffu, sc, o);
            if (lane >= o) sc += x;
        }
        const int wtot = __shfl_sync(0xffffffffu, sc, 31);
        int basew = 0;
        if (lane == 31) basew = atomicAdd(&scnt, wtot);
        basew = __shfl_sync(0xffffffffu, basew, 31);

        int posn = basew + (sc - cc);
#pragma unroll
        for (int j = 0; j < 4; j++) {
            if (vv[j] <= T) {
                unsigned sv = __float_as_uint(vv[j]);
                sv ^= (unsigned)((int)sv >> 31) | 0x80000000u;     // sortable
                if (posn < CAND_CAP)
                    scand[posn] = ((ull)sv << 12) | (unsigned)(nt * 128 + of * 4 + j);
                posn++;
            }
        }
    }
    __syncthreads();

    // ---- warp 0: exact sorted extraction of 16 smallest keys ----
    if (wrp == 0) {
        int cnt = scnt; if (cnt > CAND_CAP) cnt = CAND_CAP;
        const int nslots = (cnt + 31) >> 5;

        ull best = ~0ull; int bslot = -1;
        for (int i = 0; i < nslots; i++) {
            int sl = lane + i * 32;
            if (sl < cnt) { ull kk = scand[sl]; if (kk < best) { best = kk; bslot = sl; } }
        }
        for (int k = 0; k < K_; k++) {
            ull r2 = best;
#pragma unroll
            for (int o = 16; o > 0; o >>= 1) {
                ull x = __shfl_xor_sync(0xffffffffu, r2, o);
                r2 = (x < r2) ? x : r2;
            }
            if (lane == 0) snbr[k] = (int)(r2 & 0xfffu);
            if (best == r2) {                       // unique owner rescans
                scand[bslot] = ~0ull;
                best = ~0ull; bslot = -1;
                for (int i = 0; i < nslots; i++) {
                    int sl = lane + i * 32;
                    if (sl < cnt) { ull kk = scand[sl]; if (kk < best) { best = kk; bslot = sl; } }
                }
            }
        }
    }
    __syncthreads();

    // ---- fused gather + BN-folded max-pool + positions/batch ----
    const size_t OFF_POS   = (size_t)B_ * M_ * COUT_;
    const size_t OFF_BATCH = OFF_POS + (size_t)B_ * M_ * 3;
    const int b = q >> 10;

    if (t < COUT_) {
        const float* hb = g_h + (size_t)b * N_ * COUT_;
        float mx = -__int_as_float(0x7f800000);
        float mn =  __int_as_float(0x7f800000);
#pragma unroll
        for (int k = 0; k < K_; k++) {
            float val = hb[(size_t)snbr[k] * COUT_ + t];
            mx = fmaxf(mx, val);
            mn = fminf(mn, val);
        }
        const float sc2 = g_scale[t];
        out[(size_t)q * COUT_ + t] = fmaf(sc2, (sc2 >= 0.f) ? mx : mn, g_shift[t]);
    } else {
        int r2 = t - COUT_;
        if (r2 < 3) {
            int fi = g_fps[q];
            out[OFF_POS + (size_t)q * 3 + r2] = pos[((size_t)b * N_ + fi) * 3 + r2];
        }
        if (r2 == 3) out[OFF_BATCH + q] = (float)b;
    }
}

// =====================================================================
// launch
// =====================================================================
extern "C" void kernel_launch(void* const* d_in, const int* in_sizes, int n_in,
                              void* d_out, int out_size)
{
    const float* features  = (const float*)d_in[0];
    const float* positions = (const float*)d_in[1];
    // d_in[2] = batch (int64): values deterministic (b), unused
    const float* W     = (const float*)d_in[3];
    const float* bias  = (const float*)d_in[4];
    const float* gamma = (const float*)d_in[5];
    const float* beta  = (const float*)d_in[6];
    float* out = (float*)d_out;

    const int mega_smem = 2 * 64 * 128 * 4;          // 64 KB
    cudaFuncSetAttribute(mega_kernel, cudaFuncAttributeMaxDynamicSharedMemorySize, mega_smem);

    mega_kernel<<<MEGA_BLKS, 256, mega_smem>>>(positions, features, W, bias,
                                               gamma, beta);
    topk_gather_kernel<<<B_ * M_, 256>>>(positions, out);
}